// round 1
// baseline (speedup 1.0000x reference)
#include <cuda_runtime.h>
#include <math.h>

#define BB 128
#define LL 512
#define DD 768
#define JJ 32
#define SS 33      // J+1 segments
#define DM 200
#define DF 200
#define ROWS (BB*SS)   // 4224
#define CHUNK 32

// ---------------- scratch (no allocations allowed) ----------------
__device__ float g_pooled[ROWS * DD];   // [B*S, 768]
__device__ float g_x0[ROWS * DM];       // fc1 output
__device__ float g_qkv[ROWS * 3 * DM];  // qkv
__device__ float g_att[ROWS * DM];      // attention output (pre out-proj)
__device__ float g_y[ROWS * DM];        // pre-LN buffer
__device__ float g_x1[ROWS * DM];       // post-LN1
__device__ float g_f[ROWS * DM];        // ffn hidden
__device__ float g_x2[ROWS * DM];       // post-LN2

// =====================================================================
// Kernel 1: fused fc5 scores + per-segment softmax + weighted pooling.
// One block per (b, s). Reads hidden_state exactly once (HBM-bound).
// =====================================================================
__global__ void pool_kernel(const float* __restrict__ hidden,
                            const int* __restrict__ cidx,
                            const float* __restrict__ fc5_w,
                            const float* __restrict__ fc5_b,
                            float* __restrict__ pooled) {
    extern __shared__ float sm[];
    float* s_w      = sm;                       // [768]
    float* s_rows   = sm + DD;                  // [CHUNK][768]
    float* s_scores = s_rows + CHUNK * DD;      // [CHUNK]

    int blk = blockIdx.x;
    int b = blk / SS, s = blk % SS;
    int t0 = (s == 0)  ? 0  : cidx[b * JJ + s - 1];
    int t1 = (s == JJ) ? LL : cidx[b * JJ + s];

    int tid = threadIdx.x;
    int lane = tid & 31, wid = tid >> 5;

    for (int i = tid; i < DD; i += 256) s_w[i] = fc5_w[i];
    __syncthreads();

    const int d0 = tid, d1 = tid + 256, d2 = tid + 512;
    float acc0 = 0.f, acc1 = 0.f, acc2 = 0.f;
    float m = -INFINITY, l = 0.f;

    for (int c0 = t0; c0 < t1; c0 += CHUNK) {
        int nt = min(CHUNK, t1 - c0);
        // warps stage token rows into smem + compute fc5 dot per token
        for (int tok = wid; tok < nt; tok += 8) {
            const float* row = hidden + ((long)b * LL + (c0 + tok)) * DD;
            float pd = 0.f;
            #pragma unroll
            for (int j = 0; j < 24; j++) {
                int d = lane + 32 * j;
                float v = row[d];
                s_rows[tok * DD + d] = v;
                pd += v * s_w[d];
            }
            #pragma unroll
            for (int o = 16; o > 0; o >>= 1)
                pd += __shfl_xor_sync(0xffffffffu, pd, o);
            if (lane == 0) s_scores[tok] = pd + fc5_b[0];
        }
        __syncthreads();

        // online softmax update (redundant per-thread, identical results)
        float cm = -INFINITY;
        for (int t = 0; t < nt; t++) cm = fmaxf(cm, s_scores[t]);
        float nm = fmaxf(m, cm);
        float sc = (m == -INFINITY) ? 0.f : __expf(m - nm);
        acc0 *= sc; acc1 *= sc; acc2 *= sc; l *= sc;
        for (int t = 0; t < nt; t++) {
            float p = __expf(s_scores[t] - nm);
            l += p;
            acc0 += p * s_rows[t * DD + d0];
            acc1 += p * s_rows[t * DD + d1];
            acc2 += p * s_rows[t * DD + d2];
        }
        m = nm;
        __syncthreads();
    }

    float inv = 1.f / l;
    float* out = pooled + (long)blk * DD;
    out[d0] = acc0 * inv;
    out[d1] = acc1 * inv;
    out[d2] = acc2 * inv;
}

// =====================================================================
// Generic fp32 GEMM: C[M,N] = A[M,K] @ W[N,K]^T (+bias)(+res)(relu?)
// 64x64 tile, 256 threads, 4x4 per thread, K-step 16.
// =====================================================================
__global__ void gemm_kernel(const float* __restrict__ A,
                            const float* __restrict__ W,
                            const float* __restrict__ bias,
                            const float* __restrict__ res,
                            float* __restrict__ C,
                            int M, int N, int K, int relu) {
    __shared__ float As[64 * 17];
    __shared__ float Ws[64 * 17];
    int tid = threadIdx.x;
    int tx = tid & 15, ty = tid >> 4;
    int m0 = blockIdx.x * 64, n0 = blockIdx.y * 64;
    float acc[4][4] = {};

    for (int k0 = 0; k0 < K; k0 += 16) {
        #pragma unroll
        for (int i = 0; i < 4; i++) {
            int l = tid + 256 * i;
            int mm = l >> 4, kk = l & 15;
            int gk = k0 + kk;
            int gm = m0 + mm;
            As[mm * 17 + kk] = (gm < M && gk < K) ? A[(long)gm * K + gk] : 0.f;
            int gn = n0 + mm;
            Ws[mm * 17 + kk] = (gn < N && gk < K) ? W[(long)gn * K + gk] : 0.f;
        }
        __syncthreads();
        #pragma unroll
        for (int k = 0; k < 16; k++) {
            float a[4], w[4];
            #pragma unroll
            for (int i = 0; i < 4; i++) a[i] = As[(ty * 4 + i) * 17 + k];
            #pragma unroll
            for (int j = 0; j < 4; j++) w[j] = Ws[(tx * 4 + j) * 17 + k];
            #pragma unroll
            for (int i = 0; i < 4; i++)
                #pragma unroll
                for (int j = 0; j < 4; j++)
                    acc[i][j] += a[i] * w[j];
        }
        __syncthreads();
    }

    #pragma unroll
    for (int i = 0; i < 4; i++) {
        int gm = m0 + ty * 4 + i;
        if (gm >= M) continue;
        #pragma unroll
        for (int j = 0; j < 4; j++) {
            int gn = n0 + tx * 4 + j;
            if (gn >= N) continue;
            float v = acc[i][j];
            if (bias) v += bias[gn];
            if (res)  v += res[(long)gm * N + gn];
            if (relu) v = fmaxf(v, 0.f);
            C[(long)gm * N + gn] = v;
        }
    }
}

// =====================================================================
// Kernel: single-head attention over S=33 tokens per batch (one block/batch)
// =====================================================================
#define KP 201  // padded pitch for conflict-free smem
__global__ void attn_kernel(const float* __restrict__ qkv,
                            float* __restrict__ att) {
    extern __shared__ float sm[];
    float* sq = sm;                 // [33][200]
    float* sk = sq + SS * DM;       // [33][201]
    float* sv = sk + SS * KP;       // [33][201]
    float* sp = sv + SS * KP;       // [33][33]

    int b = blockIdx.x, tid = threadIdx.x;
    for (int i = tid; i < SS * 3 * DM; i += 256) {
        int s = i / (3 * DM), c = i % (3 * DM);
        float v = qkv[((long)b * SS + s) * (3 * DM) + c];
        if (c < DM)          sq[s * DM + c] = v;
        else if (c < 2 * DM) sk[s * KP + (c - DM)] = v;
        else                 sv[s * KP + (c - 2 * DM)] = v;
    }
    __syncthreads();

    const float scale = 0.0707106781186547524f; // 1/sqrt(200)
    for (int idx = tid; idx < SS * SS; idx += 256) {
        int i = idx / SS, j = idx % SS;
        const float* qr = sq + i * DM;
        const float* kr = sk + j * KP;
        float d = 0.f;
        #pragma unroll 8
        for (int c = 0; c < DM; c++) d += qr[c] * kr[c];
        sp[idx] = d * scale;
    }
    __syncthreads();

    if (tid < SS) {
        float* row = sp + tid * SS;
        float mx = -INFINITY;
        for (int j = 0; j < SS; j++) mx = fmaxf(mx, row[j]);
        float sum = 0.f;
        for (int j = 0; j < SS; j++) { float e = __expf(row[j] - mx); row[j] = e; sum += e; }
        float inv = 1.f / sum;
        for (int j = 0; j < SS; j++) row[j] *= inv;
    }
    __syncthreads();

    for (int idx = tid; idx < SS * DM; idx += 256) {
        int i = idx / DM, c = idx % DM;
        float d = 0.f;
        #pragma unroll 8
        for (int j = 0; j < SS; j++) d += sp[i * SS + j] * sv[j * KP + c];
        att[((long)b * SS + i) * DM + c] = d;
    }
}

// =====================================================================
// LayerNorm over DM=200, one warp per row
// =====================================================================
__global__ void ln_kernel(const float* __restrict__ x,
                          const float* __restrict__ g,
                          const float* __restrict__ bta,
                          float* __restrict__ y, int M) {
    int row = blockIdx.x * 8 + (threadIdx.x >> 5);
    int lane = threadIdx.x & 31;
    if (row >= M) return;
    const float* xr = x + (long)row * DM;
    float vals[7];
    float s = 0.f;
    #pragma unroll
    for (int i = 0; i < 7; i++) {
        int d = lane + 32 * i;
        vals[i] = (d < DM) ? xr[d] : 0.f;
        s += vals[i];
    }
    #pragma unroll
    for (int o = 16; o > 0; o >>= 1) s += __shfl_xor_sync(0xffffffffu, s, o);
    float mean = s / (float)DM;
    float vs = 0.f;
    #pragma unroll
    for (int i = 0; i < 7; i++) {
        int d = lane + 32 * i;
        if (d < DM) { float t = vals[i] - mean; vs += t * t; }
    }
    #pragma unroll
    for (int o = 16; o > 0; o >>= 1) vs += __shfl_xor_sync(0xffffffffu, vs, o);
    float inv = rsqrtf(vs / (float)DM + 1e-5f);
    float* yr = y + (long)row * DM;
    #pragma unroll
    for (int i = 0; i < 7; i++) {
        int d = lane + 32 * i;
        if (d < DM) yr[d] = (vals[i] - mean) * inv * g[d] + bta[d];
    }
}

// =====================================================================
// Final head: out[b, s-1, c] = fc_w[c,:200]·x[b,0] + fc_w[c,200:]·x[b,s] + fc_b[c]
// =====================================================================
__global__ void head_kernel(const float* __restrict__ x,
                            const float* __restrict__ fcw,
                            const float* __restrict__ fcb,
                            float* __restrict__ out) {
    int b = blockIdx.x;
    int tid = threadIdx.x;          // 64 threads: (s-1, c)
    int srow = 1 + (tid >> 1), c = tid & 1;
    const float* x0 = x + (long)b * SS * DM;
    const float* xs = x0 + (long)srow * DM;
    const float* w  = fcw + c * (2 * DM);
    float d = fcb[c];
    for (int k = 0; k < DM; k++) d += w[k] * x0[k];
    for (int k = 0; k < DM; k++) d += w[DM + k] * xs[k];
    out[((long)b * (SS - 1) + (srow - 1)) * 2 + c] = d;
}

// =====================================================================
// Launch
// =====================================================================
extern "C" void kernel_launch(void* const* d_in, const int* in_sizes, int n_in,
                              void* d_out, int out_size) {
    const float* hidden     = (const float*)d_in[0];
    const int*   cidx       = (const int*)  d_in[1];
    const float* fc5_w      = (const float*)d_in[2];
    const float* fc5_b      = (const float*)d_in[3];
    const float* fc1_w      = (const float*)d_in[4];
    const float* fc1_b      = (const float*)d_in[5];
    const float* attn_in_w  = (const float*)d_in[6];
    const float* attn_in_b  = (const float*)d_in[7];
    const float* attn_out_w = (const float*)d_in[8];
    const float* attn_out_b = (const float*)d_in[9];
    const float* ln1_g      = (const float*)d_in[10];
    const float* ln1_b      = (const float*)d_in[11];
    const float* lin1_w     = (const float*)d_in[12];
    const float* lin1_b     = (const float*)d_in[13];
    const float* lin2_w     = (const float*)d_in[14];
    const float* lin2_b     = (const float*)d_in[15];
    const float* ln2_g      = (const float*)d_in[16];
    const float* ln2_b      = (const float*)d_in[17];
    const float* fc_w       = (const float*)d_in[18];
    const float* fc_b       = (const float*)d_in[19];
    float* out = (float*)d_out;

    float *pooled, *x0, *qkv, *att, *y, *x1, *f, *x2;
    cudaGetSymbolAddress((void**)&pooled, g_pooled);
    cudaGetSymbolAddress((void**)&x0,  g_x0);
    cudaGetSymbolAddress((void**)&qkv, g_qkv);
    cudaGetSymbolAddress((void**)&att, g_att);
    cudaGetSymbolAddress((void**)&y,   g_y);
    cudaGetSymbolAddress((void**)&x1,  g_x1);
    cudaGetSymbolAddress((void**)&f,   g_f);
    cudaGetSymbolAddress((void**)&x2,  g_x2);

    const int pool_smem = (DD + CHUNK * DD + CHUNK) * (int)sizeof(float);        // ~101.5 KB
    const int attn_smem = (SS * DM + 2 * SS * KP + SS * SS) * (int)sizeof(float); // ~83.8 KB
    cudaFuncSetAttribute(pool_kernel, cudaFuncAttributeMaxDynamicSharedMemorySize, pool_smem);
    cudaFuncSetAttribute(attn_kernel, cudaFuncAttributeMaxDynamicSharedMemorySize, attn_smem);

    // 1. fused scores + segment softmax + pooling  (single pass over 201 MB)
    pool_kernel<<<BB * SS, 256, pool_smem>>>(hidden, cidx, fc5_w, fc5_b, pooled);

    // 2. fc1: [4224,768] @ [768,200]^T
    gemm_kernel<<<dim3(66, 4), 256>>>(pooled, fc1_w, fc1_b, nullptr, x0, ROWS, DM, DD, 0);

    // 3. qkv: [4224,200] @ [200,600]^T
    gemm_kernel<<<dim3(66, 10), 256>>>(x0, attn_in_w, attn_in_b, nullptr, qkv, ROWS, 3 * DM, DM, 0);

    // 4. single-head attention per batch
    attn_kernel<<<BB, 256, attn_smem>>>(qkv, att);

    // 5. out-proj + residual -> LN1
    gemm_kernel<<<dim3(66, 4), 256>>>(att, attn_out_w, attn_out_b, x0, y, ROWS, DM, DM, 0);
    ln_kernel<<<(ROWS + 7) / 8, 256>>>(y, ln1_g, ln1_b, x1, ROWS);

    // 6. FFN: relu(x@lin1^T) @ lin2^T + residual -> LN2
    gemm_kernel<<<dim3(66, 4), 256>>>(x1, lin1_w, lin1_b, nullptr, f, ROWS, DM, DM, 1);
    gemm_kernel<<<dim3(66, 4), 256>>>(f, lin2_w, lin2_b, x1, y, ROWS, DM, DM, 0);
    ln_kernel<<<(ROWS + 7) / 8, 256>>>(y, ln2_g, ln2_b, x2, ROWS);

    // 7. classifier head
    head_kernel<<<BB, 64>>>(x2, fc_w, fc_b, out);
}

// round 2
// speedup vs baseline: 1.3308x; 1.3308x over previous
#include <cuda_runtime.h>
#include <math.h>

#define BB 128
#define LL 512
#define DD 768
#define JJ 32
#define SS 33      // J+1 segments
#define DM 200
#define DF 200
#define ROWS (BB*SS)   // 4224
#define CHUNK 32

// ---------------- scratch (no allocations allowed) ----------------
__device__ float g_pooled[ROWS * DD];   // [B*S, 768]
__device__ float g_x0[ROWS * DM];       // fc1 output
__device__ float g_qkv[ROWS * 3 * DM];  // qkv
__device__ float g_att[ROWS * DM];      // attention output (pre out-proj)
__device__ float g_y[ROWS * DM];        // pre-LN buffer
__device__ float g_x1[ROWS * DM];       // post-LN1
__device__ float g_f[ROWS * DM];        // ffn hidden
__device__ float g_x2[ROWS * DM];       // post-LN2

// =====================================================================
// Kernel 1: fused fc5 scores + per-segment softmax + weighted pooling.
// One block per (b, s). Reads hidden_state exactly once. float4 paths.
// =====================================================================
__global__ void pool_kernel(const float* __restrict__ hidden,
                            const int* __restrict__ cidx,
                            const float* __restrict__ fc5_w,
                            const float* __restrict__ fc5_b,
                            float* __restrict__ pooled) {
    extern __shared__ float sm[];
    float* s_w      = sm;                       // [768]
    float* s_rows   = sm + DD;                  // [CHUNK][768]
    float* s_scores = s_rows + CHUNK * DD;      // [CHUNK]

    int blk = blockIdx.x;
    int b = blk / SS, s = blk % SS;
    int t0 = (s == 0)  ? 0  : cidx[b * JJ + s - 1];
    int t1 = (s == JJ) ? LL : cidx[b * JJ + s];

    int tid = threadIdx.x;
    int lane = tid & 31, wid = tid >> 5;

    for (int i = tid; i < DD / 4; i += 256)
        ((float4*)s_w)[i] = ((const float4*)fc5_w)[i];
    __syncthreads();

    const int d0 = tid, d1 = tid + 256, d2 = tid + 512;
    float acc0 = 0.f, acc1 = 0.f, acc2 = 0.f;
    float m = -INFINITY, l = 0.f;

    for (int c0 = t0; c0 < t1; c0 += CHUNK) {
        int nt = min(CHUNK, t1 - c0);
        // warps stage token rows into smem (float4) + fc5 dot per token
        for (int tok = wid; tok < nt; tok += 8) {
            const float4* row4 = (const float4*)(hidden + ((long)b * LL + (c0 + tok)) * DD);
            float4* dst4 = (float4*)(s_rows + tok * DD);
            const float4* w4 = (const float4*)s_w;
            float pd = 0.f;
            #pragma unroll
            for (int j = 0; j < 6; j++) {
                int q = lane + 32 * j;           // 0..191 float4 slots
                float4 v = row4[q];
                dst4[q] = v;
                float4 w = w4[q];
                pd += v.x * w.x + v.y * w.y + v.z * w.z + v.w * w.w;
            }
            #pragma unroll
            for (int o = 16; o > 0; o >>= 1)
                pd += __shfl_xor_sync(0xffffffffu, pd, o);
            if (lane == 0) s_scores[tok] = pd + fc5_b[0];
        }
        __syncthreads();

        // online softmax update (redundant per-thread, identical results)
        float cm = -INFINITY;
        for (int t = 0; t < nt; t++) cm = fmaxf(cm, s_scores[t]);
        float nm = fmaxf(m, cm);
        float sc = (m == -INFINITY) ? 0.f : __expf(m - nm);
        acc0 *= sc; acc1 *= sc; acc2 *= sc; l *= sc;
        for (int t = 0; t < nt; t++) {
            float p = __expf(s_scores[t] - nm);
            l += p;
            acc0 += p * s_rows[t * DD + d0];
            acc1 += p * s_rows[t * DD + d1];
            acc2 += p * s_rows[t * DD + d2];
        }
        m = nm;
        __syncthreads();
    }

    float inv = 1.f / l;
    float* out = pooled + (long)blk * DD;
    out[d0] = acc0 * inv;
    out[d1] = acc1 * inv;
    out[d2] = acc2 * inv;
}

// =====================================================================
// fp32 GEMM: C[M,N] = A[M,K] @ W[N,K]^T (+bias)(+res)(relu?)
// 64x64 tile, 256 threads, 4x4/thread. k-major smem, float4 LDS, no conflicts.
// =====================================================================
#define TK 16
#define SPITCH 68   // 64 + 4 pad, multiple of 4 for LDS.128 alignment
__global__ void gemm_kernel(const float* __restrict__ A,
                            const float* __restrict__ W,
                            const float* __restrict__ bias,
                            const float* __restrict__ res,
                            float* __restrict__ C,
                            int M, int N, int K, int relu) {
    __shared__ float As[TK * SPITCH];
    __shared__ float Ws[TK * SPITCH];
    int tid = threadIdx.x;
    int tx = tid & 15, ty = tid >> 4;
    int m0 = blockIdx.x * 64, n0 = blockIdx.y * 64;

    // loader coords: each thread loads one float4 along K
    int lm = tid >> 2;        // 0..63 row within tile
    int lk = (tid & 3) * 4;   // 0,4,8,12

    float acc[4][4] = {};

    for (int k0 = 0; k0 < K; k0 += TK) {
        // load A tile (transpose to k-major)
        {
            int gm = m0 + lm;
            float4 a = make_float4(0.f, 0.f, 0.f, 0.f);
            if (gm < M) {
                const float* p = A + (long)gm * K + k0 + lk;
                if (k0 + lk + 3 < K) a = *(const float4*)p;
                else {
                    if (k0 + lk + 0 < K) a.x = p[0];
                    if (k0 + lk + 1 < K) a.y = p[1];
                    if (k0 + lk + 2 < K) a.z = p[2];
                    if (k0 + lk + 3 < K) a.w = p[3];
                }
            }
            As[(lk + 0) * SPITCH + lm] = a.x;
            As[(lk + 1) * SPITCH + lm] = a.y;
            As[(lk + 2) * SPITCH + lm] = a.z;
            As[(lk + 3) * SPITCH + lm] = a.w;
        }
        // load W tile (transpose to k-major)
        {
            int gn = n0 + lm;
            float4 w = make_float4(0.f, 0.f, 0.f, 0.f);
            if (gn < N) {
                const float* p = W + (long)gn * K + k0 + lk;
                if (k0 + lk + 3 < K) w = *(const float4*)p;
                else {
                    if (k0 + lk + 0 < K) w.x = p[0];
                    if (k0 + lk + 1 < K) w.y = p[1];
                    if (k0 + lk + 2 < K) w.z = p[2];
                    if (k0 + lk + 3 < K) w.w = p[3];
                }
            }
            Ws[(lk + 0) * SPITCH + lm] = w.x;
            Ws[(lk + 1) * SPITCH + lm] = w.y;
            Ws[(lk + 2) * SPITCH + lm] = w.z;
            Ws[(lk + 3) * SPITCH + lm] = w.w;
        }
        __syncthreads();

        #pragma unroll
        for (int k = 0; k < TK; k++) {
            float4 a4 = *(const float4*)&As[k * SPITCH + ty * 4];
            float4 w4 = *(const float4*)&Ws[k * SPITCH + tx * 4];
            float a[4] = {a4.x, a4.y, a4.z, a4.w};
            float w[4] = {w4.x, w4.y, w4.z, w4.w};
            #pragma unroll
            for (int i = 0; i < 4; i++)
                #pragma unroll
                for (int j = 0; j < 4; j++)
                    acc[i][j] += a[i] * w[j];
        }
        __syncthreads();
    }

    #pragma unroll
    for (int i = 0; i < 4; i++) {
        int gm = m0 + ty * 4 + i;
        if (gm >= M) continue;
        #pragma unroll
        for (int j = 0; j < 4; j++) {
            int gn = n0 + tx * 4 + j;
            if (gn >= N) continue;
            float v = acc[i][j];
            if (bias) v += bias[gn];
            if (res)  v += res[(long)gm * N + gn];
            if (relu) v = fmaxf(v, 0.f);
            C[(long)gm * N + gn] = v;
        }
    }
}

// =====================================================================
// Single-head attention over S=33 tokens per batch. float4 everywhere.
// =====================================================================
#define PP 34   // score row pitch
__global__ void attn_kernel(const float* __restrict__ qkv,
                            float* __restrict__ att) {
    extern __shared__ float sm[];
    float* sq = sm;                 // [33][200]
    float* sk = sq + SS * DM;       // [33][200]
    float* sv = sk + SS * DM;       // [33][200]
    float* sp = sv + SS * DM;       // [33][34]

    int b = blockIdx.x, tid = threadIdx.x;
    int lane = tid & 31, wid = tid >> 5;

    // load qkv: 33*600 floats = 4950 float4
    const float4* src4 = (const float4*)(qkv + (long)b * SS * 3 * DM);
    for (int i = tid; i < SS * 3 * DM / 4; i += 256) {
        int s = i / 150, c4 = i % 150;
        float4 v = src4[i];
        int c = c4 * 4;
        float* dst;
        if (c < DM)          dst = sq + s * DM + c;
        else if (c < 2 * DM) dst = sk + s * DM + (c - DM);
        else                 dst = sv + s * DM + (c - 2 * DM);
        *(float4*)dst = v;
    }
    __syncthreads();

    // scores: tasks = (i, j-tile of 4): 33 * 9 = 297
    const float scale = 0.0707106781186547524f; // 1/sqrt(200)
    for (int idx = tid; idx < SS * 9; idx += 256) {
        int i = idx / 9, jt = idx % 9;
        int j0 = jt * 4;
        float a0 = 0.f, a1 = 0.f, a2 = 0.f, a3 = 0.f;
        const float4* q4 = (const float4*)(sq + i * DM);
        const float4* k0p = (const float4*)(sk + (j0 + 0) * DM);
        const float4* k1p = (const float4*)(sk + (j0 + 1 < SS ? j0 + 1 : j0) * DM);
        const float4* k2p = (const float4*)(sk + (j0 + 2 < SS ? j0 + 2 : j0) * DM);
        const float4* k3p = (const float4*)(sk + (j0 + 3 < SS ? j0 + 3 : j0) * DM);
        #pragma unroll 5
        for (int c = 0; c < DM / 4; c++) {
            float4 q = q4[c];
            float4 k0v = k0p[c], k1v = k1p[c], k2v = k2p[c], k3v = k3p[c];
            a0 += q.x * k0v.x + q.y * k0v.y + q.z * k0v.z + q.w * k0v.w;
            a1 += q.x * k1v.x + q.y * k1v.y + q.z * k1v.z + q.w * k1v.w;
            a2 += q.x * k2v.x + q.y * k2v.y + q.z * k2v.z + q.w * k2v.w;
            a3 += q.x * k3v.x + q.y * k3v.y + q.z * k3v.z + q.w * k3v.w;
        }
        sp[i * PP + j0] = a0 * scale;
        if (j0 + 1 < SS) sp[i * PP + j0 + 1] = a1 * scale;
        if (j0 + 2 < SS) sp[i * PP + j0 + 2] = a2 * scale;
        if (j0 + 3 < SS) sp[i * PP + j0 + 3] = a3 * scale;
    }
    __syncthreads();

    // softmax: one warp per row
    for (int i = wid; i < SS; i += 8) {
        float* row = sp + i * PP;
        float v0 = (lane < SS) ? row[lane] : -INFINITY;
        float v1 = (lane + 32 < SS) ? row[lane + 32] : -INFINITY;
        float mx = fmaxf(v0, v1);
        #pragma unroll
        for (int o = 16; o > 0; o >>= 1)
            mx = fmaxf(mx, __shfl_xor_sync(0xffffffffu, mx, o));
        float e0 = (lane < SS) ? __expf(v0 - mx) : 0.f;
        float e1 = (lane + 32 < SS) ? __expf(v1 - mx) : 0.f;
        float sum = e0 + e1;
        #pragma unroll
        for (int o = 16; o > 0; o >>= 1)
            sum += __shfl_xor_sync(0xffffffffu, sum, o);
        float inv = 1.f / sum;
        if (lane < SS) row[lane] = e0 * inv;
        if (lane + 32 < SS) row[lane + 32] = e1 * inv;
    }
    __syncthreads();

    // PV: outputs (i, c4): 33 * 50 = 1650 float4s
    for (int idx = tid; idx < SS * (DM / 4); idx += 256) {
        int i = idx / (DM / 4), c4 = idx % (DM / 4);
        float4 acc = make_float4(0.f, 0.f, 0.f, 0.f);
        const float* prow = sp + i * PP;
        #pragma unroll 3
        for (int j = 0; j < SS; j++) {
            float p = prow[j];
            float4 v = *(const float4*)(sv + j * DM + c4 * 4);
            acc.x += p * v.x; acc.y += p * v.y; acc.z += p * v.z; acc.w += p * v.w;
        }
        *(float4*)(att + ((long)b * SS + i) * DM + c4 * 4) = acc;
    }
}

// =====================================================================
// LayerNorm over DM=200, one warp per row
// =====================================================================
__global__ void ln_kernel(const float* __restrict__ x,
                          const float* __restrict__ g,
                          const float* __restrict__ bta,
                          float* __restrict__ y, int M) {
    int row = blockIdx.x * 8 + (threadIdx.x >> 5);
    int lane = threadIdx.x & 31;
    if (row >= M) return;
    const float* xr = x + (long)row * DM;
    float vals[7];
    float s = 0.f;
    #pragma unroll
    for (int i = 0; i < 7; i++) {
        int d = lane + 32 * i;
        vals[i] = (d < DM) ? xr[d] : 0.f;
        s += vals[i];
    }
    #pragma unroll
    for (int o = 16; o > 0; o >>= 1) s += __shfl_xor_sync(0xffffffffu, s, o);
    float mean = s / (float)DM;
    float vs = 0.f;
    #pragma unroll
    for (int i = 0; i < 7; i++) {
        int d = lane + 32 * i;
        if (d < DM) { float t = vals[i] - mean; vs += t * t; }
    }
    #pragma unroll
    for (int o = 16; o > 0; o >>= 1) vs += __shfl_xor_sync(0xffffffffu, vs, o);
    float inv = rsqrtf(vs / (float)DM + 1e-5f);
    float* yr = y + (long)row * DM;
    #pragma unroll
    for (int i = 0; i < 7; i++) {
        int d = lane + 32 * i;
        if (d < DM) yr[d] = (vals[i] - mean) * inv * g[d] + bta[d];
    }
}

// =====================================================================
// Final head: warp-per-output with shuffle reduction
// out[b, s-1, c] = fc_w[c,:200].x[b,0] + fc_w[c,200:].x[b,s] + fc_b[c]
// =====================================================================
__global__ void head_kernel(const float* __restrict__ x,
                            const float* __restrict__ fcw,
                            const float* __restrict__ fcb,
                            float* __restrict__ out) {
    int b = blockIdx.x;
    int lane = threadIdx.x & 31, wid = threadIdx.x >> 5;
    const float* x0 = x + (long)b * SS * DM;
    for (int oid = wid; oid < (SS - 1) * 2; oid += 8) {
        int srow = 1 + (oid >> 1), c = oid & 1;
        const float* xs = x0 + (long)srow * DM;
        const float* w  = fcw + c * (2 * DM);
        float d = 0.f;
        #pragma unroll
        for (int i = 0; i < 7; i++) {
            int k = lane + 32 * i;
            if (k < DM) d += w[k] * x0[k] + w[DM + k] * xs[k];
        }
        #pragma unroll
        for (int o = 16; o > 0; o >>= 1)
            d += __shfl_xor_sync(0xffffffffu, d, o);
        if (lane == 0)
            out[((long)b * (SS - 1) + (srow - 1)) * 2 + c] = d + fcb[c];
    }
}

// =====================================================================
// Launch
// =====================================================================
extern "C" void kernel_launch(void* const* d_in, const int* in_sizes, int n_in,
                              void* d_out, int out_size) {
    const float* hidden     = (const float*)d_in[0];
    const int*   cidx       = (const int*)  d_in[1];
    const float* fc5_w      = (const float*)d_in[2];
    const float* fc5_b      = (const float*)d_in[3];
    const float* fc1_w      = (const float*)d_in[4];
    const float* fc1_b      = (const float*)d_in[5];
    const float* attn_in_w  = (const float*)d_in[6];
    const float* attn_in_b  = (const float*)d_in[7];
    const float* attn_out_w = (const float*)d_in[8];
    const float* attn_out_b = (const float*)d_in[9];
    const float* ln1_g      = (const float*)d_in[10];
    const float* ln1_b      = (const float*)d_in[11];
    const float* lin1_w     = (const float*)d_in[12];
    const float* lin1_b     = (const float*)d_in[13];
    const float* lin2_w     = (const float*)d_in[14];
    const float* lin2_b     = (const float*)d_in[15];
    const float* ln2_g      = (const float*)d_in[16];
    const float* ln2_b      = (const float*)d_in[17];
    const float* fc_w       = (const float*)d_in[18];
    const float* fc_b       = (const float*)d_in[19];
    float* out = (float*)d_out;

    float *pooled, *x0, *qkv, *att, *y, *x1, *f, *x2;
    cudaGetSymbolAddress((void**)&pooled, g_pooled);
    cudaGetSymbolAddress((void**)&x0,  g_x0);
    cudaGetSymbolAddress((void**)&qkv, g_qkv);
    cudaGetSymbolAddress((void**)&att, g_att);
    cudaGetSymbolAddress((void**)&y,   g_y);
    cudaGetSymbolAddress((void**)&x1,  g_x1);
    cudaGetSymbolAddress((void**)&f,   g_f);
    cudaGetSymbolAddress((void**)&x2,  g_x2);

    const int pool_smem = (DD + CHUNK * DD + CHUNK) * (int)sizeof(float);       // ~101.5 KB
    const int attn_smem = (3 * SS * DM + SS * PP) * (int)sizeof(float);         // ~83.6 KB
    cudaFuncSetAttribute(pool_kernel, cudaFuncAttributeMaxDynamicSharedMemorySize, pool_smem);
    cudaFuncSetAttribute(attn_kernel, cudaFuncAttributeMaxDynamicSharedMemorySize, attn_smem);

    // 1. fused scores + segment softmax + pooling (single pass over 201 MB)
    pool_kernel<<<BB * SS, 256, pool_smem>>>(hidden, cidx, fc5_w, fc5_b, pooled);

    // 2. fc1: [4224,768] @ [768,200]^T
    gemm_kernel<<<dim3(66, 4), 256>>>(pooled, fc1_w, fc1_b, nullptr, x0, ROWS, DM, DD, 0);

    // 3. qkv: [4224,200] @ [200,600]^T
    gemm_kernel<<<dim3(66, 10), 256>>>(x0, attn_in_w, attn_in_b, nullptr, qkv, ROWS, 3 * DM, DM, 0);

    // 4. single-head attention per batch
    attn_kernel<<<BB, 256, attn_smem>>>(qkv, att);

    // 5. out-proj + residual -> LN1
    gemm_kernel<<<dim3(66, 4), 256>>>(att, attn_out_w, attn_out_b, x0, y, ROWS, DM, DM, 0);
    ln_kernel<<<(ROWS + 7) / 8, 256>>>(y, ln1_g, ln1_b, x1, ROWS);

    // 6. FFN: relu(x@lin1^T) @ lin2^T + residual -> LN2
    gemm_kernel<<<dim3(66, 4), 256>>>(x1, lin1_w, lin1_b, nullptr, f, ROWS, DM, DM, 1);
    gemm_kernel<<<dim3(66, 4), 256>>>(f, lin2_w, lin2_b, x1, y, ROWS, DM, DM, 0);
    ln_kernel<<<(ROWS + 7) / 8, 256>>>(y, ln2_g, ln2_b, x2, ROWS);

    // 7. classifier head
    head_kernel<<<BB, 256>>>(x2, fc_w, fc_b, out);
}